// round 8
// baseline (speedup 1.0000x reference)
#include <cuda_runtime.h>
#include <cuda_fp16.h>
#include <math.h>
#include <stdint.h>

#define BATCH 4096
#define DIM   768
#define NCLS  10

#define BM 128
#define BN 256
#define BK 64                 // 64 halves = 128B per row-chunk
#define NKIT (DIM / BK)       // 12
#define NCTA_TAML 272         // sum_{c2=0..15} (2*c2+2)
#define NCE_BLK (BATCH / 8)   // 512
#define NPART 8               // centroid partials

// dynamic smem layout for k_taml (bytes). All tiles have 128B rows.
#define OFF_A0   0
#define OFF_A1   (BM * 128)                      // 16384
#define OFF_B0   (2 * BM * 128)                  // 32768
#define OFF_B1   (2 * BM * 128 + BN * 128)       // 65536
#define OFF_MISC (2 * BM * 128 + 2 * BN * 128)   // 98304
#define OFF_STHR (OFF_MISC)
#define OFF_LROW (OFF_MISC + 512)
#define OFF_LCOL (OFF_MISC + 1024)
#define OFF_WRED (OFF_MISC + 2048)               // 8 floats warp partials
#define DYN_SMEM (OFF_MISC + 2112)

__device__ __forceinline__ int clampc(int v) {
    return v < 0 ? 0 : (v >= NCLS ? NCLS - 1 : v);
}
__device__ __forceinline__ uint32_t s2u(const void* p) {
    uint32_t a;
    asm("{ .reg .u64 t; cvta.to.shared.u64 t, %1; cvt.u32.u64 %0, t; }" : "=r"(a) : "l"(p));
    return a;
}

#define LDSM4(r0, r1, r2, r3, addr) \
    asm volatile("ldmatrix.sync.aligned.m8n8.x4.shared.b16 {%0,%1,%2,%3}, [%4];" \
                 : "=r"(r0), "=r"(r1), "=r"(r2), "=r"(r3) : "r"(addr))

#define MMA_F16(d, a, b0, b1) \
    asm volatile("mma.sync.aligned.m16n8k16.row.col.f32.f16.f16.f32 " \
                 "{%0,%1,%2,%3},{%4,%5,%6,%7},{%8,%9},{%0,%1,%2,%3};" \
                 : "+f"((d)[0]), "+f"((d)[1]), "+f"((d)[2]), "+f"((d)[3]) \
                 : "r"((a)[0]), "r"((a)[1]), "r"((a)[2]), "r"((a)[3]), \
                   "r"(b0), "r"(b1))

#define CPA16(dst, src) \
    asm volatile("cp.async.cg.shared.global [%0], [%1], 16;" :: "r"(dst), "l"(src) : "memory")
#define CPCOMMIT() asm volatile("cp.async.commit_group;" ::: "memory")
#define CPWAIT(n)  asm volatile("cp.async.wait_group %0;" :: "n"(n) : "memory")

// ---------------- scratch (all write-before-read; no init kernel) ----------
__device__ __half g_enorm[BATCH * DIM];          // fp16 normalized embeddings
__device__ float g_cents_part[NPART * NCLS * DIM]; // per-rowblock class sums
__device__ float g_ce_part[NCE_BLK];             // per-block ce partials
__device__ float g_taml_part[NCTA_TAML];         // per-CTA taml partials

// ---------------- CE + row normalization (stores fp16 enorm) ----------------
__global__ __launch_bounds__(256) void k_ce_norm(
    const float* __restrict__ logits,
    const int* __restrict__ labels,
    const float* __restrict__ emb)
{
    __shared__ float wce[8];
    const unsigned FULL = 0xffffffffu;
    int warp = threadIdx.x >> 5;
    int lane = threadIdx.x & 31;
    int row  = blockIdx.x * 8 + warp;

    const float* e = emb + (size_t)row * DIM;
    float v[DIM / 32];
    float ss = 0.0f;
#pragma unroll
    for (int i = 0; i < DIM / 32; i++) { v[i] = e[lane + 32 * i]; ss += v[i] * v[i]; }
#pragma unroll
    for (int o = 16; o; o >>= 1) ss += __shfl_xor_sync(FULL, ss, o);
    float inv = 1.0f / fmaxf(sqrtf(ss), 1e-12f);
    __half* outp = g_enorm + (size_t)row * DIM;
#pragma unroll
    for (int i = 0; i < DIM / 32; i++) outp[lane + 32 * i] = __float2half_rn(v[i] * inv);

    int lab = clampc(labels[row]);
    float lg = (lane < NCLS) ? logits[row * NCLS + lane] : -INFINITY;
    float m = lg;
#pragma unroll
    for (int o = 16; o; o >>= 1) m = fmaxf(m, __shfl_xor_sync(FULL, m, o));
    float p = (lane < NCLS) ? expf(lg - m) : 0.0f;
    float s = p;
#pragma unroll
    for (int o = 16; o; o >>= 1) s += __shfl_xor_sync(FULL, s, o);
    float lse = logf(s) + m;
    float target = __shfl_sync(FULL, lg, lab);
    if (lane == 0) wce[warp] = lse - target;
    __syncthreads();
    if (threadIdx.x == 0) {
        float c = 0.0f;
#pragma unroll
        for (int w = 0; w < 8; w++) c += wce[w];
        g_ce_part[blockIdx.x] = c;
    }
}

// ---------------- per-class centroid partial sums (no atomics) -------------
// grid (3, NPART): x = 256-col slab, y = 512-row slab
__global__ __launch_bounds__(256) void k_centsum(
    const float* __restrict__ emb,
    const int* __restrict__ labels)
{
    __shared__ float acc[NCLS * 256];
    int tid = threadIdx.x;
#pragma unroll
    for (int c = 0; c < NCLS; c++) acc[c * 256 + tid] = 0.0f;
    __syncthreads();

    int col = blockIdx.x * 256 + tid;
    int r0  = blockIdx.y * (BATCH / NPART);
#pragma unroll 4
    for (int r = r0; r < r0 + BATCH / NPART; r++) {
        int lab = clampc(labels[r]);
        acc[lab * 256 + tid] += emb[(size_t)r * DIM + col];
    }
    __syncthreads();
    float* dst = g_cents_part + (size_t)blockIdx.y * NCLS * DIM;
#pragma unroll
    for (int c = 0; c < NCLS; c++)
        dst[c * DIM + col] = acc[c * 256 + tid];
}

// ---------------- TAML: fp16 mma.sync GEMM + fused margin epilogue ---------
__device__ __forceinline__ void stage_tiles(
    uint32_t sb, int buf, const __half* Ag, const __half* Bg, int kb, int tid)
{
    uint32_t aoff = buf ? OFF_A1 : OFF_A0;
    uint32_t boff = buf ? OFF_B1 : OFF_B0;
#pragma unroll
    for (int q = 0; q < 4; q++) {
        int f = tid + q * 256;
        int row = f >> 3, ch = f & 7;
        const __half* src = Ag + (size_t)row * DIM + kb + ch * 8;
        uint32_t dst = sb + aoff + row * 128 + (((uint32_t)(ch ^ (row & 7))) << 4);
        CPA16(dst, src);
    }
#pragma unroll
    for (int q = 0; q < 8; q++) {
        int f = tid + q * 256;
        int row = f >> 3, ch = f & 7;
        const __half* src = Bg + (size_t)row * DIM + kb + ch * 8;
        uint32_t dst = sb + boff + row * 128 + (((uint32_t)(ch ^ (row & 7))) << 4);
        CPA16(dst, src);
    }
}

__global__ __launch_bounds__(256) void k_taml(
    const int* __restrict__ labels,
    const float* __restrict__ topo)
{
    extern __shared__ __align__(1024) char sm[];
    uint32_t sb = s2u(sm);
    int tid = threadIdx.x;
    int lane = tid & 31;
    int wid  = tid >> 5;
    int warpM = wid & 1;   // 64-row halves
    int warpN = wid >> 1;  // 64-col strips

    // decode CTA -> (r in 128-row tiles, c2 in 256-col tiles), r <= 2*c2+1
    int bid = blockIdx.x;
    int c2 = 0;
    while (bid >= (2 * c2 + 2)) { bid -= (2 * c2 + 2); c2++; }
    int r = bid;
    int rowA0 = r * BM;
    int rowB0 = c2 * BN;

    float* sthrS = (float*)(sm + OFF_STHR);
    int*   lrowS = (int*)(sm + OFF_LROW);
    int*   lcolS = (int*)(sm + OFF_LCOL);
    float* wredS = (float*)(sm + OFF_WRED);
    if (tid < NCLS * NCLS) sthrS[tid] = 1.0f - topo[tid];
    if (tid < BM) lrowS[tid] = clampc(labels[rowA0 + tid]);
    lcolS[tid] = clampc(labels[rowB0 + tid]);

    const __half* Ag = g_enorm + (size_t)rowA0 * DIM;
    const __half* Bg = g_enorm + (size_t)rowB0 * DIM;

    float acc[4][8][4];
#pragma unroll
    for (int i = 0; i < 4; i++)
#pragma unroll
        for (int j = 0; j < 8; j++)
#pragma unroll
            for (int k = 0; k < 4; k++) acc[i][j][k] = 0.0f;

    stage_tiles(sb, 0, Ag, Bg, 0, tid);
    CPCOMMIT();

    for (int it = 0; it < NKIT; it++) {
        int buf = it & 1;
        if (it + 1 < NKIT) {
            stage_tiles(sb, buf ^ 1, Ag, Bg, (it + 1) * BK, tid);
            CPCOMMIT();
            CPWAIT(1);
        } else {
            CPWAIT(0);
        }
        __syncthreads();

        uint32_t ab = sb + (buf ? OFF_A1 : OFF_A0);
        uint32_t bb = sb + (buf ? OFF_B1 : OFF_B0);
#pragma unroll
        for (int ks = 0; ks < 4; ks++) {
            uint32_t a[4][4];
#pragma unroll
            for (int mf = 0; mf < 4; mf++) {
                int arow = warpM * 64 + mf * 16 + ((lane >> 3) & 1) * 8 + (lane & 7);
                int kch = ks * 2 + (lane >> 4);
                uint32_t ad = ab + arow * 128 + (((uint32_t)(kch ^ (arow & 7))) << 4);
                LDSM4(a[mf][0], a[mf][1], a[mf][2], a[mf][3], ad);
            }
            uint32_t b[4][4];
#pragma unroll
            for (int p = 0; p < 4; p++) {
                int col = warpN * 64 + p * 16 + (lane >> 4) * 8 + (lane & 7);
                int kch = ks * 2 + ((lane >> 3) & 1);
                uint32_t bd = bb + col * 128 + (((uint32_t)(kch ^ (col & 7))) << 4);
                LDSM4(b[p][0], b[p][1], b[p][2], b[p][3], bd);
            }
#pragma unroll
            for (int mf = 0; mf < 4; mf++)
#pragma unroll
                for (int nf = 0; nf < 8; nf++) {
                    uint32_t b0 = b[nf >> 1][(nf & 1) * 2];
                    uint32_t b1 = b[nf >> 1][(nf & 1) * 2 + 1];
                    MMA_F16(acc[mf][nf], a[mf], b0, b1);
                }
        }
        __syncthreads();
    }

    // ---- epilogue: relu margin on register accumulators ----
    float lsum = 0.0f;
#pragma unroll
    for (int mf = 0; mf < 4; mf++) {
        int row0 = warpM * 64 + mf * 16 + (lane >> 2);
        int la0 = lrowS[row0];
        int la1 = lrowS[row0 + 8];
        int ig0 = rowA0 + row0;
#pragma unroll
        for (int nf = 0; nf < 8; nf++) {
            int col = warpN * 64 + nf * 8 + (lane & 3) * 2;
            int lb0 = lcolS[col], lb1 = lcolS[col + 1];
            int jg0 = rowB0 + col;
            if (jg0 > ig0 && la0 != lb0)
                lsum += fmaxf(acc[mf][nf][0] - sthrS[la0 * NCLS + lb0], 0.0f);
            if (jg0 + 1 > ig0 && la0 != lb1)
                lsum += fmaxf(acc[mf][nf][1] - sthrS[la0 * NCLS + lb1], 0.0f);
            if (jg0 > ig0 + 8 && la1 != lb0)
                lsum += fmaxf(acc[mf][nf][2] - sthrS[la1 * NCLS + lb0], 0.0f);
            if (jg0 + 1 > ig0 + 8 && la1 != lb1)
                lsum += fmaxf(acc[mf][nf][3] - sthrS[la1 * NCLS + lb1], 0.0f);
        }
    }
    lsum *= 2.0f;  // strict upper triangle counted once; matrix holds both orders

    const unsigned FULL = 0xffffffffu;
#pragma unroll
    for (int o = 16; o; o >>= 1) lsum += __shfl_xor_sync(FULL, lsum, o);
    if (lane == 0) wredS[wid] = lsum;
    __syncthreads();
    if (tid == 0) {
        float t = 0.0f;
#pragma unroll
        for (int w = 0; w < 8; w++) t += wredS[w];
        g_taml_part[blockIdx.x] = t;
    }
}

// ---------------- fused TALS + final combine (one 1024-thread block) -------
__global__ __launch_bounds__(1024) void k_final(
    const int* __restrict__ labels,
    const float* __restrict__ topo,
    float* __restrict__ out)
{
    __shared__ float sc[NCLS * DIM];
    __shared__ float ed[128];
    __shared__ float cnts[NCLS];
    __shared__ float red[4];
    int tid = threadIdx.x;
    const unsigned FULL = 0xffffffffu;

    if (tid < NCLS) cnts[tid] = 0.0f;
    if (tid < 128) ed[tid] = 0.0f;
    __syncthreads();

    // class counts
    for (int i = tid; i < BATCH; i += 1024)
        atomicAdd(&cnts[clampc(labels[i])], 1.0f);
    __syncthreads();

    // centroids = sum of NPART partials / count
    for (int i = tid; i < NCLS * DIM; i += 1024) {
        float s = 0.0f;
#pragma unroll
        for (int y = 0; y < NPART; y++) s += g_cents_part[y * NCLS * DIM + i];
        int c = i / DIM;
        sc[i] = s * __frcp_rn(fmaxf(cnts[c], 1.0f));
    }
    __syncthreads();

    // pairwise centroid distances
    int warp = tid >> 5, lane = tid & 31;
    for (int p = warp; p < NCLS * NCLS; p += 32) {
        int i = p / NCLS, j = p % NCLS;
        float s = 0.0f;
        for (int d = lane; d < DIM; d += 32) {
            float df = sc[i * DIM + d] - sc[j * DIM + d];
            s += df * df;
        }
#pragma unroll
        for (int o = 16; o; o >>= 1) s += __shfl_xor_sync(FULL, s, o);
        if (lane == 0) ed[p] = sqrtf(s + 1e-12f);
    }
    __syncthreads();

    if (warp == 0) {            // tals: max + mse
        float m0 = fmaxf(ed[lane], fmaxf(ed[lane + 32], fmaxf(ed[lane + 64], ed[lane + 96])));
#pragma unroll
        for (int o = 16; o; o >>= 1) m0 = fmaxf(m0, __shfl_xor_sync(FULL, m0, o));
        float inv = 1.0f / (m0 + 1e-8f);
        float mse = 0.0f;
        for (int p = lane; p < NCLS * NCLS; p += 32) {
            float v = ed[p] * inv - topo[p];
            mse += v * v;
        }
#pragma unroll
        for (int o = 16; o; o >>= 1) mse += __shfl_xor_sync(FULL, mse, o);
        if (lane == 0) red[0] = mse / (float)(NCLS * NCLS);
    } else if (warp == 1) {     // ce partial sum
        float s = 0.0f;
        for (int i = lane; i < NCE_BLK; i += 32) s += g_ce_part[i];
#pragma unroll
        for (int o = 16; o; o >>= 1) s += __shfl_xor_sync(FULL, s, o);
        if (lane == 0) red[1] = s;
    } else if (warp == 2) {     // taml partial sum
        float s = 0.0f;
        for (int i = lane; i < NCTA_TAML; i += 32) s += g_taml_part[i];
#pragma unroll
        for (int o = 16; o; o >>= 1) s += __shfl_xor_sync(FULL, s, o);
        if (lane == 0) red[2] = s;
    }
    __syncthreads();

    if (tid == 0) {
        float s2 = 0.0f;
#pragma unroll
        for (int cc = 0; cc < NCLS; cc++) s2 += cnts[cc] * cnts[cc];
        float nvalid = (float)BATCH * (float)BATCH - s2;
        float taml = red[2] / fmaxf(nvalid, 1.0f);
        float ce   = red[1] / (float)BATCH;
        float tals = red[0];
        out[0] = ce + 0.5f * tals + 0.5f * taml;
        out[1] = ce;
        out[2] = tals;
        out[3] = taml;
    }
}

extern "C" void kernel_launch(void* const* d_in, const int* in_sizes, int n_in,
                              void* d_out, int out_size) {
    const float* logits = (const float*)d_in[0];
    const int*   labels = (const int*)d_in[1];
    const float* emb    = (const float*)d_in[2];
    const float* topo   = (const float*)d_in[3];
    float* out = (float*)d_out;

    cudaFuncSetAttribute(k_taml, cudaFuncAttributeMaxDynamicSharedMemorySize, DYN_SMEM);

    k_ce_norm<<<NCE_BLK, 256>>>(logits, labels, emb);      // 0
    k_centsum<<<dim3(3, NPART), 256>>>(emb, labels);       // 1
    k_taml<<<NCTA_TAML, 256, DYN_SMEM>>>(labels, topo);    // 2
    k_final<<<1, 1024>>>(labels, topo, out);               // 3
}

// round 9
// speedup vs baseline: 1.4453x; 1.4453x over previous
#include <cuda_runtime.h>
#include <cuda_fp16.h>
#include <math.h>
#include <stdint.h>

#define BATCH 4096
#define DIM   768
#define NCLS  10

#define BM 128
#define BN 256
#define BK 64                 // 64 halves = 128B per row-chunk
#define NKIT (DIM / BK)       // 12
#define NCTA_TAML 272         // sum_{c2=0..15} (2*c2+2)
#define NCE_BLK (BATCH / 8)   // 512
#define NPART 16              // centroid partials
#define NCS_BLK (3 * NPART)   // 48 centsum blocks
#define ROWS_PER_PART (BATCH / NPART)  // 256

// dynamic smem layout for k_taml (bytes). All tiles have 128B rows.
#define OFF_A0   0
#define OFF_A1   (BM * 128)
#define OFF_B0   (2 * BM * 128)
#define OFF_B1   (2 * BM * 128 + BN * 128)
#define OFF_MISC (2 * BM * 128 + 2 * BN * 128)
#define OFF_STHR (OFF_MISC)
#define OFF_LROW (OFF_MISC + 512)
#define OFF_LCOL (OFF_MISC + 1024)
#define OFF_WRED (OFF_MISC + 2048)
#define DYN_SMEM (OFF_MISC + 2112)

__device__ __forceinline__ int clampc(int v) {
    return v < 0 ? 0 : (v >= NCLS ? NCLS - 1 : v);
}
__device__ __forceinline__ uint32_t s2u(const void* p) {
    uint32_t a;
    asm("{ .reg .u64 t; cvta.to.shared.u64 t, %1; cvt.u32.u64 %0, t; }" : "=r"(a) : "l"(p));
    return a;
}

#define LDSM4(r0, r1, r2, r3, addr) \
    asm volatile("ldmatrix.sync.aligned.m8n8.x4.shared.b16 {%0,%1,%2,%3}, [%4];" \
                 : "=r"(r0), "=r"(r1), "=r"(r2), "=r"(r3) : "r"(addr))

#define MMA_F16(d, a, b0, b1) \
    asm volatile("mma.sync.aligned.m16n8k16.row.col.f32.f16.f16.f32 " \
                 "{%0,%1,%2,%3},{%4,%5,%6,%7},{%8,%9},{%0,%1,%2,%3};" \
                 : "+f"((d)[0]), "+f"((d)[1]), "+f"((d)[2]), "+f"((d)[3]) \
                 : "r"((a)[0]), "r"((a)[1]), "r"((a)[2]), "r"((a)[3]), \
                   "r"(b0), "r"(b1))

#define CPA16(dst, src) \
    asm volatile("cp.async.cg.shared.global [%0], [%1], 16;" :: "r"(dst), "l"(src) : "memory")
#define CPCOMMIT() asm volatile("cp.async.commit_group;" ::: "memory")
#define CPWAIT(n)  asm volatile("cp.async.wait_group %0;" :: "n"(n) : "memory")

// ---------------- scratch (all write-before-read; no init kernel) ----------
__device__ __half g_enorm[BATCH * DIM];
__device__ float g_cents_part[NPART * NCLS * DIM];
__device__ float g_ce_part[NCE_BLK];
__device__ float g_taml_part[NCTA_TAML];

// ---------------- fused: CE + normalize (blocks 0..511), centsum (512..559) -
__global__ __launch_bounds__(256) void k_prep(
    const float* __restrict__ logits,
    const int* __restrict__ labels,
    const float* __restrict__ emb)
{
    __shared__ float acc[4][NCLS * 256];   // 40 KB (centsum); reused as wce (ce)
    const unsigned FULL = 0xffffffffu;
    int tid = threadIdx.x;
    int b = blockIdx.x;

    if (b < NCE_BLK) {
        // -------- CE + row normalization --------
        float* wce = &acc[0][0];
        int warp = tid >> 5;
        int lane = tid & 31;
        int row  = b * 8 + warp;

        const float* e = emb + (size_t)row * DIM;
        float v[DIM / 32];
        float ss = 0.0f;
#pragma unroll
        for (int i = 0; i < DIM / 32; i++) { v[i] = e[lane + 32 * i]; ss += v[i] * v[i]; }
#pragma unroll
        for (int o = 16; o; o >>= 1) ss += __shfl_xor_sync(FULL, ss, o);
        float inv = 1.0f / fmaxf(sqrtf(ss), 1e-12f);
        __half* outp = g_enorm + (size_t)row * DIM;
#pragma unroll
        for (int i = 0; i < DIM / 32; i++) outp[lane + 32 * i] = __float2half_rn(v[i] * inv);

        int lab = clampc(labels[row]);
        float lg = (lane < NCLS) ? logits[row * NCLS + lane] : -INFINITY;
        float m = lg;
#pragma unroll
        for (int o = 16; o; o >>= 1) m = fmaxf(m, __shfl_xor_sync(FULL, m, o));
        float p = (lane < NCLS) ? expf(lg - m) : 0.0f;
        float s = p;
#pragma unroll
        for (int o = 16; o; o >>= 1) s += __shfl_xor_sync(FULL, s, o);
        float lse = logf(s) + m;
        float target = __shfl_sync(FULL, lg, lab);
        if (lane == 0) wce[warp] = lse - target;
        __syncthreads();
        if (tid == 0) {
            float c = 0.0f;
#pragma unroll
            for (int w = 0; w < 8; w++) c += wce[w];
            g_ce_part[b] = c;
        }
    } else {
        // -------- centroid partial sums: 4 interleaved accumulator sets -----
        int q  = b - NCE_BLK;
        int bx = q % 3;            // column slab (3 x 256 = 768)
        int by = q / 3;            // row slab (NPART)
        int col = bx * 256 + tid;
        int r0  = by * ROWS_PER_PART;

        // zero own column of all 4 sets (column-private: no sync needed)
        float* af = &acc[0][0];
#pragma unroll
        for (int k = 0; k < 4 * NCLS; k++) af[k * 256 + tid] = 0.0f;

        const float* ecol = emb + col;
#pragma unroll 2
        for (int r = 0; r < ROWS_PER_PART; r += 4) {
#pragma unroll
            for (int qq = 0; qq < 4; qq++) {
                int rr = r0 + r + qq;
                int lab = clampc(labels[rr]);
                acc[qq][lab * 256 + tid] += ecol[(size_t)rr * DIM];
            }
        }

        float* dst = g_cents_part + (size_t)by * NCLS * DIM;
#pragma unroll
        for (int c = 0; c < NCLS; c++) {
            float s = acc[0][c * 256 + tid] + acc[1][c * 256 + tid]
                    + acc[2][c * 256 + tid] + acc[3][c * 256 + tid];
            dst[c * DIM + col] = s;
        }
    }
}

// ---------------- TAML: fp16 mma.sync GEMM + fused margin epilogue ---------
__device__ __forceinline__ void stage_tiles(
    uint32_t sb, int buf, const __half* Ag, const __half* Bg, int kb, int tid)
{
    uint32_t aoff = buf ? OFF_A1 : OFF_A0;
    uint32_t boff = buf ? OFF_B1 : OFF_B0;
#pragma unroll
    for (int q = 0; q < 4; q++) {
        int f = tid + q * 256;
        int row = f >> 3, ch = f & 7;
        const __half* src = Ag + (size_t)row * DIM + kb + ch * 8;
        uint32_t dst = sb + aoff + row * 128 + (((uint32_t)(ch ^ (row & 7))) << 4);
        CPA16(dst, src);
    }
#pragma unroll
    for (int q = 0; q < 8; q++) {
        int f = tid + q * 256;
        int row = f >> 3, ch = f & 7;
        const __half* src = Bg + (size_t)row * DIM + kb + ch * 8;
        uint32_t dst = sb + boff + row * 128 + (((uint32_t)(ch ^ (row & 7))) << 4);
        CPA16(dst, src);
    }
}

__global__ __launch_bounds__(256) void k_taml(
    const int* __restrict__ labels,
    const float* __restrict__ topo)
{
    extern __shared__ __align__(1024) char sm[];
    uint32_t sb = s2u(sm);
    int tid = threadIdx.x;
    int lane = tid & 31;
    int wid  = tid >> 5;
    int warpM = wid & 1;
    int warpN = wid >> 1;

    int bid = blockIdx.x;
    int c2 = 0;
    while (bid >= (2 * c2 + 2)) { bid -= (2 * c2 + 2); c2++; }
    int r = bid;
    int rowA0 = r * BM;
    int rowB0 = c2 * BN;

    float* sthrS = (float*)(sm + OFF_STHR);
    int*   lrowS = (int*)(sm + OFF_LROW);
    int*   lcolS = (int*)(sm + OFF_LCOL);
    float* wredS = (float*)(sm + OFF_WRED);
    if (tid < NCLS * NCLS) sthrS[tid] = 1.0f - topo[tid];
    if (tid < BM) lrowS[tid] = clampc(labels[rowA0 + tid]);
    lcolS[tid] = clampc(labels[rowB0 + tid]);

    const __half* Ag = g_enorm + (size_t)rowA0 * DIM;
    const __half* Bg = g_enorm + (size_t)rowB0 * DIM;

    float acc[4][8][4];
#pragma unroll
    for (int i = 0; i < 4; i++)
#pragma unroll
        for (int j = 0; j < 8; j++)
#pragma unroll
            for (int k = 0; k < 4; k++) acc[i][j][k] = 0.0f;

    stage_tiles(sb, 0, Ag, Bg, 0, tid);
    CPCOMMIT();

    for (int it = 0; it < NKIT; it++) {
        int buf = it & 1;
        if (it + 1 < NKIT) {
            stage_tiles(sb, buf ^ 1, Ag, Bg, (it + 1) * BK, tid);
            CPCOMMIT();
            CPWAIT(1);
        } else {
            CPWAIT(0);
        }
        __syncthreads();

        uint32_t ab = sb + (buf ? OFF_A1 : OFF_A0);
        uint32_t bb = sb + (buf ? OFF_B1 : OFF_B0);
#pragma unroll
        for (int ks = 0; ks < 4; ks++) {
            uint32_t a[4][4];
#pragma unroll
            for (int mf = 0; mf < 4; mf++) {
                int arow = warpM * 64 + mf * 16 + ((lane >> 3) & 1) * 8 + (lane & 7);
                int kch = ks * 2 + (lane >> 4);
                uint32_t ad = ab + arow * 128 + (((uint32_t)(kch ^ (arow & 7))) << 4);
                LDSM4(a[mf][0], a[mf][1], a[mf][2], a[mf][3], ad);
            }
            uint32_t b[4][4];
#pragma unroll
            for (int p = 0; p < 4; p++) {
                int col = warpN * 64 + p * 16 + (lane >> 4) * 8 + (lane & 7);
                int kch = ks * 2 + ((lane >> 3) & 1);
                uint32_t bd = bb + col * 128 + (((uint32_t)(kch ^ (col & 7))) << 4);
                LDSM4(b[p][0], b[p][1], b[p][2], b[p][3], bd);
            }
#pragma unroll
            for (int mf = 0; mf < 4; mf++)
#pragma unroll
                for (int nf = 0; nf < 8; nf++) {
                    uint32_t b0 = b[nf >> 1][(nf & 1) * 2];
                    uint32_t b1 = b[nf >> 1][(nf & 1) * 2 + 1];
                    MMA_F16(acc[mf][nf], a[mf], b0, b1);
                }
        }
        __syncthreads();
    }

    float lsum = 0.0f;
#pragma unroll
    for (int mf = 0; mf < 4; mf++) {
        int row0 = warpM * 64 + mf * 16 + (lane >> 2);
        int la0 = lrowS[row0];
        int la1 = lrowS[row0 + 8];
        int ig0 = rowA0 + row0;
#pragma unroll
        for (int nf = 0; nf < 8; nf++) {
            int col = warpN * 64 + nf * 8 + (lane & 3) * 2;
            int lb0 = lcolS[col], lb1 = lcolS[col + 1];
            int jg0 = rowB0 + col;
            if (jg0 > ig0 && la0 != lb0)
                lsum += fmaxf(acc[mf][nf][0] - sthrS[la0 * NCLS + lb0], 0.0f);
            if (jg0 + 1 > ig0 && la0 != lb1)
                lsum += fmaxf(acc[mf][nf][1] - sthrS[la0 * NCLS + lb1], 0.0f);
            if (jg0 > ig0 + 8 && la1 != lb0)
                lsum += fmaxf(acc[mf][nf][2] - sthrS[la1 * NCLS + lb0], 0.0f);
            if (jg0 + 1 > ig0 + 8 && la1 != lb1)
                lsum += fmaxf(acc[mf][nf][3] - sthrS[la1 * NCLS + lb1], 0.0f);
        }
    }
    lsum *= 2.0f;

    const unsigned FULL = 0xffffffffu;
#pragma unroll
    for (int o = 16; o; o >>= 1) lsum += __shfl_xor_sync(FULL, lsum, o);
    if (lane == 0) wredS[wid] = lsum;
    __syncthreads();
    if (tid == 0) {
        float t = 0.0f;
#pragma unroll
        for (int w = 0; w < 8; w++) t += wredS[w];
        g_taml_part[blockIdx.x] = t;
    }
}

// ---------------- fused TALS + final combine (one 1024-thread block) -------
__global__ __launch_bounds__(1024) void k_final(
    const int* __restrict__ labels,
    const float* __restrict__ topo,
    float* __restrict__ out)
{
    __shared__ float sc[NCLS * DIM];     // 30 KB centroids
    __shared__ float wcnt[32][NCLS];
    __shared__ float cnts[NCLS];
    __shared__ float ed[128];
    __shared__ float red[4];
    int tid = threadIdx.x;
    int warp = tid >> 5, lane = tid & 31;
    const unsigned FULL = 0xffffffffu;

    // ---- class counts via ballots (no atomics) ----
    int lab[4];
#pragma unroll
    for (int q = 0; q < 4; q++) lab[q] = clampc(labels[warp * 128 + q * 32 + lane]);
#pragma unroll
    for (int c = 0; c < NCLS; c++) {
        int cnt = 0;
#pragma unroll
        for (int q = 0; q < 4; q++) cnt += __popc(__ballot_sync(FULL, lab[q] == c));
        if (lane == 0) wcnt[warp][c] = (float)cnt;
    }
    if (tid < 128) ed[tid] = 0.0f;
    __syncthreads();
    if (tid < NCLS) {
        float s = 0.0f;
#pragma unroll
        for (int w = 0; w < 32; w++) s += wcnt[w][tid];
        cnts[tid] = s;
    }
    __syncthreads();

    // ---- centroids = sum of NPART partials / count (float4) ----
    for (int idx = tid; idx < NCLS * DIM / 4; idx += 1024) {
        float4 s = make_float4(0.f, 0.f, 0.f, 0.f);
#pragma unroll
        for (int y = 0; y < NPART; y++) {
            float4 v = *(const float4*)(g_cents_part + (size_t)y * NCLS * DIM + idx * 4);
            s.x += v.x; s.y += v.y; s.z += v.z; s.w += v.w;
        }
        int c = idx / (DIM / 4);
        float inv = __frcp_rn(fmaxf(cnts[c], 1.0f));
        float4* o4 = (float4*)(sc + idx * 4);
        *o4 = make_float4(s.x * inv, s.y * inv, s.z * inv, s.w * inv);
    }
    __syncthreads();

    // ---- pairwise centroid distances (float4, one pair per warp) ----
    for (int p = warp; p < NCLS * NCLS; p += 32) {
        int i = p / NCLS, j = p % NCLS;
        const float4* ci = (const float4*)(sc + i * DIM);
        const float4* cj = (const float4*)(sc + j * DIM);
        float s = 0.0f;
#pragma unroll
        for (int t = 0; t < DIM / 128; t++) {   // 6
            float4 a = ci[lane + 32 * t];
            float4 b = cj[lane + 32 * t];
            float dx = a.x - b.x, dy = a.y - b.y, dz = a.z - b.z, dw = a.w - b.w;
            s += dx * dx + dy * dy + dz * dz + dw * dw;
        }
#pragma unroll
        for (int o = 16; o; o >>= 1) s += __shfl_xor_sync(FULL, s, o);
        if (lane == 0) ed[p] = sqrtf(s + 1e-12f);
    }
    __syncthreads();

    if (warp == 0) {            // tals: max + mse
        float m0 = fmaxf(ed[lane], fmaxf(ed[lane + 32], fmaxf(ed[lane + 64], ed[lane + 96])));
#pragma unroll
        for (int o = 16; o; o >>= 1) m0 = fmaxf(m0, __shfl_xor_sync(FULL, m0, o));
        float inv = 1.0f / (m0 + 1e-8f);
        float mse = 0.0f;
        for (int p = lane; p < NCLS * NCLS; p += 32) {
            float v = ed[p] * inv - topo[p];
            mse += v * v;
        }
#pragma unroll
        for (int o = 16; o; o >>= 1) mse += __shfl_xor_sync(FULL, mse, o);
        if (lane == 0) red[0] = mse / (float)(NCLS * NCLS);
    } else if (warp == 1) {     // ce partial sum
        float s = 0.0f;
        for (int i = lane; i < NCE_BLK; i += 32) s += g_ce_part[i];
#pragma unroll
        for (int o = 16; o; o >>= 1) s += __shfl_xor_sync(FULL, s, o);
        if (lane == 0) red[1] = s;
    } else if (warp == 2) {     // taml partial sum
        float s = 0.0f;
        for (int i = lane; i < NCTA_TAML; i += 32) s += g_taml_part[i];
#pragma unroll
        for (int o = 16; o; o >>= 1) s += __shfl_xor_sync(FULL, s, o);
        if (lane == 0) red[2] = s;
    }
    __syncthreads();

    if (tid == 0) {
        float s2 = 0.0f;
#pragma unroll
        for (int cc = 0; cc < NCLS; cc++) s2 += cnts[cc] * cnts[cc];
        float nvalid = (float)BATCH * (float)BATCH - s2;
        float taml = red[2] / fmaxf(nvalid, 1.0f);
        float ce   = red[1] / (float)BATCH;
        float tals = red[0];
        out[0] = ce + 0.5f * tals + 0.5f * taml;
        out[1] = ce;
        out[2] = tals;
        out[3] = taml;
    }
}

extern "C" void kernel_launch(void* const* d_in, const int* in_sizes, int n_in,
                              void* d_out, int out_size) {
    const float* logits = (const float*)d_in[0];
    const int*   labels = (const int*)d_in[1];
    const float* emb    = (const float*)d_in[2];
    const float* topo   = (const float*)d_in[3];
    float* out = (float*)d_out;

    cudaFuncSetAttribute(k_taml, cudaFuncAttributeMaxDynamicSharedMemorySize, DYN_SMEM);

    k_prep<<<NCE_BLK + NCS_BLK, 256>>>(logits, labels, emb);  // 0
    k_taml<<<NCTA_TAML, 256, DYN_SMEM>>>(labels, topo);       // 1
    k_final<<<1, 1024>>>(labels, topo, out);                  // 2
}